// round 15
// baseline (speedup 1.0000x reference)
#include <cuda_runtime.h>
#include <cstdint>

// CropAndResize: image (8,256,200,200) f32 NCHW, boxes (512,4) [y1,x1,y2,x2],
// box_indices (512,) int32 -> out (512,256,14,14) f32. Bilinear, extrap 0.
//
// R15: R14 skeleton (quarter-plane staging, 4 CTAs/SM stagger) with
//  - prep entry allocation via SHARED atomics (kills L2 atomic serialization)
//  - uint4 entries with pre-baked byte/word offsets (near-zero gather decode)

#define IH 200
#define IW 200
#define CROP 14
#define NCH 256
#define NBOX 512
#define NIMG 8
#define PLANE (IH * IW)
#define POS (CROP * CROP)          // 196
#define PITCH 204                  // smem row pitch (floats); 816B rows
#define ROWB (PITCH * 4)           // 816
#define NQ 4
#define QROWS 50
#define BROWS 51
#define MAXBI 128
#define CAP (MAXBI * CROP)
#define TPB 448                    // 32 entry-groups x 14 cols
#define EGRP 32
#define CPR 50                     // 16B chunks per image row

__device__ int   d_nent[NIMG * NQ];
__device__ uint2 d_xtab[NIMG * MAXBI * CROP];   // {x0 | vx<<8, lx}
// Entry: x = o*816 | vy ; y = nid*3584 + r*14 ; z = ly ; w = slot*14 | (dy*816)<<16
__device__ uint4 d_ent[NIMG * NQ * CAP];

__global__ __launch_bounds__(NBOX) void prep_kernel(
    const float* __restrict__ boxes,
    const int*   __restrict__ box_idx)
{
    __shared__ int snb[NIMG];
    __shared__ int scnt[NIMG * NQ];
    const int n = threadIdx.x;
    if (n < NIMG) snb[n] = 0;
    if (n < NIMG * NQ) scnt[n] = 0;
    __syncthreads();

    const int img  = box_idx[n];
    const int slot = atomicAdd(&snb[img], 1);      // order irrelevant
    const float4 bq = ((const float4*)boxes)[n];   // y1,x1,y2,x2
    const float ys = (bq.z - bq.x) * (float)(IH - 1) * (1.0f / (CROP - 1));
    const float xs = (bq.w - bq.y) * (float)(IW - 1) * (1.0f / (CROP - 1));

    #pragma unroll
    for (int k = 0; k < CROP; ++k) {
        {   // x table (per box, per crop-col)
            const float v  = bq.y * (float)(IW - 1) + (float)k * xs;
            const float fl = floorf(v);
            const int x0 = (int)fminf(fmaxf(fl, 0.0f), (float)(IW - 1));
            const unsigned vx = (v >= 0.0f && v <= (float)(IW - 1)) ? 1u : 0u;
            d_xtab[(img * MAXBI + slot) * CROP + k] =
                make_uint2((unsigned)x0 | (vx << 8), __float_as_uint(v - fl));
        }
        {   // y row -> pre-baked entry in owning quarter's list
            const float v  = bq.x * (float)(IH - 1) + (float)k * ys;
            const float fl = floorf(v);
            const int y0 = (int)fminf(fmaxf(fl, 0.0f), (float)(IH - 1));
            const int q  = y0 / QROWS;                 // 0..3
            const int o  = y0 - q * QROWS;             // 0..49
            const unsigned dy = (y0 < IH - 1) ? 1u : 0u;
            const unsigned vy = (v >= 0.0f && v <= (float)(IH - 1)) ? 1u : 0u;
            const int idx = atomicAdd(&scnt[img * NQ + q], 1);   // smem atomic
            d_ent[(img * NQ + q) * CAP + idx] = make_uint4(
                (unsigned)(o * ROWB) | vy,
                (unsigned)(n * (NCH * POS) + k * CROP),
                __float_as_uint(v - fl),
                (unsigned)(slot * CROP) | ((dy * ROWB) << 16));
        }
    }
    __syncthreads();
    if (n < NIMG * NQ) d_nent[n] = scnt[n];
}

#define SM_BYTES (BROWS * ROWB)    // 41616 -> 4 CTAs/SM

__global__ __launch_bounds__(TPB, 4) void crop_resize_kernel(
    const float* __restrict__ image,
    float*       __restrict__ out)
{
    extern __shared__ float plane[];   // BROWS x PITCH, padded

    const int bx  = blockIdx.x;
    const int img = bx >> 10;          // blocks of one image adjacent
    const int ch  = (bx >> 2) & 255;
    const int q   = bx & 3;
    const int tid = threadIdx.x;

    // ---- Stage quarter-plane: sequential 16B cp.async, one commit group ----
    const int nchunk = ((q == 3) ? 50 : 51) * CPR;
    const char* srcb = (const char*)(image + ((size_t)img * NCH + ch) * PLANE
                                           + (size_t)q * QROWS * IW);
    const uint32_t smem_b = (uint32_t)__cvta_generic_to_shared(plane);
    #pragma unroll 2
    for (int i = tid; i < nchunk; i += TPB) {
        const int row = i / CPR;
        const int c16 = i - row * CPR;
        asm volatile("cp.async.cg.shared.global [%0], [%1], 16;"
                     :: "r"(smem_b + row * ROWB + c16 * 16),
                        "l"(srcb + row * (IW * 4) + c16 * 16));
    }
    asm volatile("cp.async.commit_group;");

    // Zero row pads (x0=199 pair reads land at col 200; lx=0 there).
    if (tid < BROWS) {
        float4* pad = (float4*)(plane + tid * PITCH + IW);
        *pad = make_float4(0.f, 0.f, 0.f, 0.f);
    }

    const int ne = d_nent[img * NQ + q];
    const uint4* gent = d_ent + (img * NQ + q) * CAP;
    const uint2* gxt  = d_xtab + (size_t)img * MAXBI * CROP;

    const int e0  = tid / CROP;        // 0..31
    const int col = tid - e0 * CROP;   // 0..13
    float* outb = out + (size_t)ch * POS + col;
    const char* planeb = (const char*)plane;

    asm volatile("cp.async.wait_group 0;");
    __syncthreads();

    // ---- Gather: pre-baked offsets, minimal decode ----
    for (int e = e0; e < ne; e += EGRP) {
        const uint4 E = __ldg(gent + e);
        const uint2 tx = __ldg(gxt + (E.w & 0xFFFFu) + col);

        const char* r0 = planeb + (E.x & ~1u) + (tx.x & 255u) * 4;
        const char* r1 = r0 + (E.w >> 16);
        const float tl = *(const float*)r0;
        const float tr = *(const float*)(r0 + 4);
        const float bl = *(const float*)r1;
        const float br = *(const float*)(r1 + 4);

        const float lx = __uint_as_float(tx.y);
        const float ly = __uint_as_float(E.z);
        const float top = fmaf(tr - tl, lx, tl);
        const float bot = fmaf(br - bl, lx, bl);
        float val = fmaf(bot - top, ly, top);
        if (!(E.x & (tx.x >> 8) & 1u)) val = 0.0f;

        __stcs(outb + E.y, val);
    }
}

extern "C" void kernel_launch(void* const* d_in, const int* in_sizes, int n_in,
                              void* d_out, int out_size)
{
    const float* image   = (const float*)d_in[0];
    const float* boxes   = (const float*)d_in[1];
    const int*   box_idx = (const int*)d_in[2];
    float*       out     = (float*)d_out;

    prep_kernel<<<1, NBOX>>>(boxes, box_idx);
    crop_resize_kernel<<<NIMG * NCH * NQ, TPB, SM_BYTES>>>(image, out);
}

// round 16
// speedup vs baseline: 1.1675x; 1.1675x over previous
#include <cuda_runtime.h>
#include <cstdint>

// CropAndResize: image (8,256,200,200) f32 NCHW, boxes (512,4) [y1,x1,y2,x2],
// box_indices (512,) int32 -> out (512,256,14,14) f32. Bilinear, extrap 0.
//
// R16: quarter-plane staging via ONE cp.async.bulk per block (bulk engine --
// no per-16B LSU issue cost, which capped R14/R15 at ~55% DRAM). Prep is
// parallelized: one 32-thread block per box, warp-aggregated entry slots.

#define IH 200
#define IW 200
#define CROP 14
#define NCH 256
#define NBOX 512
#define NIMG 8
#define PLANE (IH * IW)
#define POS (CROP * CROP)          // 196
#define ROWB (IW * 4)              // 800: packed smem rows (bulk copy is linear)
#define NQ 4
#define QROWS 50
#define MAXBI 128
#define CAP (MAXBI * CROP)
#define TPB 448                    // 32 entry-groups x 14 cols
#define EGRP 32

__device__ int   d_nent[NIMG * NQ];
__device__ uint2 d_xtab[NBOX * CROP];    // {x0 | vx<<8, lx}; indexed by box id
// Entry: x = o*800 | vy ; y = nid*3584 + r*14 ; z = ly ; w = nid*14 | (dy*800)<<16
__device__ uint4 d_ent[NIMG * NQ * CAP];

// One block (32 threads) per box. Lanes 0..13: x-table. Lanes 14..27: y rows,
// slots reserved with warp-aggregated atomics (<=4 global atomics per box).
__global__ __launch_bounds__(32) void prep_kernel(
    const float* __restrict__ boxes,
    const int*   __restrict__ box_idx)
{
    const int n    = blockIdx.x;
    const int lane = threadIdx.x;
    const int img  = box_idx[n];
    const float4 bq = ((const float4*)boxes)[n];   // y1,x1,y2,x2

    if (lane < CROP) {             // x-axis
        const float xs = (bq.w - bq.y) * (float)(IW - 1) * (1.0f / (CROP - 1));
        const float v  = bq.y * (float)(IW - 1) + (float)lane * xs;
        const float fl = floorf(v);
        const int x0 = (int)fminf(fmaxf(fl, 0.0f), (float)(IW - 1));
        const unsigned vx = (v >= 0.0f && v <= (float)(IW - 1)) ? 1u : 0u;
        d_xtab[n * CROP + lane] =
            make_uint2((unsigned)x0 | (vx << 8), __float_as_uint(v - fl));
    }

    const bool isy = (lane >= CROP) && (lane < 2 * CROP);
    const int  k   = lane - CROP;
    int q = -1, o = 0;
    unsigned dy = 0, vy = 0;
    float ly = 0.0f;
    if (isy) {
        const float ys = (bq.z - bq.x) * (float)(IH - 1) * (1.0f / (CROP - 1));
        const float v  = bq.x * (float)(IH - 1) + (float)k * ys;
        const float fl = floorf(v);
        const int y0 = (int)fminf(fmaxf(fl, 0.0f), (float)(IH - 1));
        q  = y0 / QROWS;
        o  = y0 - q * QROWS;
        dy = (y0 < IH - 1) ? 1u : 0u;
        vy = (v >= 0.0f && v <= (float)(IH - 1)) ? 1u : 0u;
        ly = v - fl;
    }

    #pragma unroll
    for (int qq = 0; qq < NQ; ++qq) {
        const unsigned m = __ballot_sync(0xFFFFFFFFu, isy && (q == qq));
        if (m) {
            const int leader = __ffs(m) - 1;
            int base = 0;
            if (lane == leader)
                base = atomicAdd(&d_nent[img * NQ + qq], __popc(m));
            base = __shfl_sync(0xFFFFFFFFu, base, leader);
            if (isy && q == qq) {
                const int idx = base + __popc(m & ((1u << lane) - 1u));
                d_ent[(img * NQ + qq) * CAP + idx] = make_uint4(
                    (unsigned)(o * ROWB) | vy,
                    (unsigned)(n * (NCH * POS) + k * CROP),
                    __float_as_uint(ly),
                    (unsigned)(n * CROP) | ((dy * ROWB) << 16));
            }
        }
    }
}

// smem: plane (51*800=40800 max) + 16B pad slot + mbar
#define SM_MBAR   40816
#define SM_BYTES  40832            // 4 CTAs/SM: 163KB smem

__global__ __launch_bounds__(TPB, 4) void crop_resize_kernel(
    const float* __restrict__ image,
    float*       __restrict__ out)
{
    extern __shared__ float plane[];

    const int bx  = blockIdx.x;
    const int img = bx >> 10;
    const int ch  = (bx >> 2) & 255;
    const int q   = bx & 3;
    const int tid = threadIdx.x;

    const uint32_t smem_b = (uint32_t)__cvta_generic_to_shared(plane);
    const uint32_t mbar   = smem_b + SM_MBAR;
    const unsigned bytes  = (q == 3) ? (50 * ROWB) : (51 * ROWB);   // contiguous rows

    if (tid == 0)
        asm volatile("mbarrier.init.shared.b64 [%0], 1;" :: "r"(mbar) : "memory");
    // Zero 16B past the loaded region: x0=199 pair-read on the last buffered
    // row lands there (weight lx=0 or masked; must be finite).
    if (tid == 1)
        *(float4*)((char*)plane + bytes) = make_float4(0.f, 0.f, 0.f, 0.f);
    __syncthreads();

    if (tid == 0) {
        const char* src = (const char*)(image + ((size_t)img * NCH + ch) * PLANE
                                              + (size_t)q * QROWS * IW);
        asm volatile("mbarrier.arrive.expect_tx.shared.b64 _, [%0], %1;"
                     :: "r"(mbar), "r"(bytes) : "memory");
        asm volatile(
            "cp.async.bulk.shared::cta.global.mbarrier::complete_tx::bytes "
            "[%0], [%1], %2, [%3];"
            :: "r"(smem_b), "l"(src), "r"(bytes), "r"(mbar) : "memory");
    }

    // Table pointers + per-thread decode (overlapped with bulk in flight)
    const int ne = d_nent[img * NQ + q];
    const uint4* gent = d_ent + (img * NQ + q) * CAP;

    const int e0  = tid / CROP;        // 0..31
    const int col = tid - e0 * CROP;   // 0..13
    float* outb = out + (size_t)ch * POS + col;
    const char* planeb = (const char*)plane;

    // Wait for bulk completion (phase 0)
    asm volatile(
        "{\n\t.reg .pred P;\n"
        "W%=:\n\t"
        "mbarrier.try_wait.parity.shared.b64 P, [%0], 0;\n\t"
        "@P bra D%=;\n\t"
        "bra W%=;\n"
        "D%=:\n\t}"
        :: "r"(mbar) : "memory");

    // ---- Gather: pre-baked offsets, ~7 iterations/thread ----
    for (int e = e0; e < ne; e += EGRP) {
        const uint4 E = __ldg(gent + e);
        const uint2 tx = __ldg(d_xtab + (E.w & 0xFFFFu) + col);

        const char* r0 = planeb + (E.x & ~1u) + (tx.x & 255u) * 4;
        const char* r1 = r0 + (E.w >> 16);
        const float tl = *(const float*)r0;
        const float tr = *(const float*)(r0 + 4);
        const float bl = *(const float*)r1;
        const float br = *(const float*)(r1 + 4);

        const float lx = __uint_as_float(tx.y);
        const float ly = __uint_as_float(E.z);
        const float top = fmaf(tr - tl, lx, tl);
        const float bot = fmaf(br - bl, lx, bl);
        float val = fmaf(bot - top, ly, top);
        if (!(E.x & (tx.x >> 8) & 1u)) val = 0.0f;

        __stcs(outb + E.y, val);
    }
}

extern "C" void kernel_launch(void* const* d_in, const int* in_sizes, int n_in,
                              void* d_out, int out_size)
{
    const float* image   = (const float*)d_in[0];
    const float* boxes   = (const float*)d_in[1];
    const int*   box_idx = (const int*)d_in[2];
    float*       out     = (float*)d_out;

    static void* nent_addr = nullptr;
    if (!nent_addr) {
        cudaGetSymbolAddress(&nent_addr, d_nent);
        cudaFuncSetAttribute(crop_resize_kernel,
                             cudaFuncAttributeMaxDynamicSharedMemorySize,
                             SM_BYTES);
    }

    cudaMemsetAsync(nent_addr, 0, NIMG * NQ * sizeof(int));
    prep_kernel<<<NBOX, 32>>>(boxes, box_idx);
    crop_resize_kernel<<<NIMG * NCH * NQ, TPB, SM_BYTES>>>(image, out);
}

// round 17
// speedup vs baseline: 1.2497x; 1.0704x over previous
#include <cuda_runtime.h>
#include <cstdint>

// CropAndResize: image (8,256,200,200) f32 NCHW, boxes (512,4) [y1,x1,y2,x2],
// box_indices (512,) int32 -> out (512,256,14,14) f32. Bilinear, extrap 0.
//
// R17: R16 (bulk-engine quarter staging, prebaked entry lists) + per-CTA
// depth-2 double-buffered pipeline over 4 channels of the same (image,
// quarter): bulk load of tile t+1 streams while tile t is gathered. Entry
// list is L1-resident across the 4 tiles.

#define IH 200
#define IW 200
#define CROP 14
#define NCH 256
#define NBOX 512
#define NIMG 8
#define PLANE (IH * IW)
#define POS (CROP * CROP)          // 196
#define ROWB (IW * 4)              // 800: packed smem rows
#define NQ 4
#define QROWS 50
#define MAXBI 128
#define CAP (MAXBI * CROP)
#define TPB 896                    // 64 entry-groups x 14 cols
#define EGRP 64
#define TILES 4                    // channels per CTA

__device__ int   d_nent[NIMG * NQ];
__device__ uint2 d_xtab[NBOX * CROP];    // {x0 | vx<<8, lx}; indexed by box id
// Entry: x = o*800 | vy ; y = nid*3584 + r*14 ; z = ly ; w = nid*14 | (dy*800)<<16
__device__ uint4 d_ent[NIMG * NQ * CAP];

// One block (32 threads) per box. Lanes 0..13: x-table. Lanes 14..27: y rows,
// slots reserved with warp-aggregated atomics.
__global__ __launch_bounds__(32) void prep_kernel(
    const float* __restrict__ boxes,
    const int*   __restrict__ box_idx)
{
    const int n    = blockIdx.x;
    const int lane = threadIdx.x;
    const int img  = box_idx[n];
    const float4 bq = ((const float4*)boxes)[n];   // y1,x1,y2,x2

    if (lane < CROP) {             // x-axis
        const float xs = (bq.w - bq.y) * (float)(IW - 1) * (1.0f / (CROP - 1));
        const float v  = bq.y * (float)(IW - 1) + (float)lane * xs;
        const float fl = floorf(v);
        const int x0 = (int)fminf(fmaxf(fl, 0.0f), (float)(IW - 1));
        const unsigned vx = (v >= 0.0f && v <= (float)(IW - 1)) ? 1u : 0u;
        d_xtab[n * CROP + lane] =
            make_uint2((unsigned)x0 | (vx << 8), __float_as_uint(v - fl));
    }

    const bool isy = (lane >= CROP) && (lane < 2 * CROP);
    const int  k   = lane - CROP;
    int q = -1, o = 0;
    unsigned dy = 0, vy = 0;
    float ly = 0.0f;
    if (isy) {
        const float ys = (bq.z - bq.x) * (float)(IH - 1) * (1.0f / (CROP - 1));
        const float v  = bq.x * (float)(IH - 1) + (float)k * ys;
        const float fl = floorf(v);
        const int y0 = (int)fminf(fmaxf(fl, 0.0f), (float)(IH - 1));
        q  = y0 / QROWS;
        o  = y0 - q * QROWS;
        dy = (y0 < IH - 1) ? 1u : 0u;
        vy = (v >= 0.0f && v <= (float)(IH - 1)) ? 1u : 0u;
        ly = v - fl;
    }

    #pragma unroll
    for (int qq = 0; qq < NQ; ++qq) {
        const unsigned m = __ballot_sync(0xFFFFFFFFu, isy && (q == qq));
        if (m) {
            const int leader = __ffs(m) - 1;
            int base = 0;
            if (lane == leader)
                base = atomicAdd(&d_nent[img * NQ + qq], __popc(m));
            base = __shfl_sync(0xFFFFFFFFu, base, leader);
            if (isy && q == qq) {
                const int idx = base + __popc(m & ((1u << lane) - 1u));
                d_ent[(img * NQ + qq) * CAP + idx] = make_uint4(
                    (unsigned)(o * ROWB) | vy,
                    (unsigned)(n * (NCH * POS) + k * CROP),
                    __float_as_uint(ly),
                    (unsigned)(n * CROP) | ((dy * ROWB) << 16));
            }
        }
    }
}

// smem: 2 buffers (51*800 + 16B pad each), then 2 mbarriers
#define BUFSTRIDE 40832            // 40800 data + 16 pad + 16 align
#define SM_MBAR   (2 * BUFSTRIDE)  // 81664
#define SM_BYTES  (SM_MBAR + 32)   // 81696 -> 2 CTAs/SM

__global__ __launch_bounds__(TPB, 2) void crop_resize_kernel(
    const float* __restrict__ image,
    float*       __restrict__ out)
{
    extern __shared__ char smem[];

    const int bx  = blockIdx.x;                // 2048 blocks
    const int img = bx >> 8;                   // 256 blocks/image
    const int ch0 = (((bx >> 2) & 63) << 2);   // 4-channel group
    const int q   = bx & 3;
    const int tid = threadIdx.x;

    const uint32_t smem_b = (uint32_t)__cvta_generic_to_shared(smem);
    const uint32_t mbar   = smem_b + SM_MBAR;
    const unsigned bytes  = (q == 3) ? (50 * ROWB) : (51 * ROWB);

    if (tid == 0) {
        asm volatile("mbarrier.init.shared.b64 [%0], 1;" :: "r"(mbar)     : "memory");
        asm volatile("mbarrier.init.shared.b64 [%0], 1;" :: "r"(mbar + 8) : "memory");
    }
    // Zero 16B past loaded region in both buffers (x0=199 pair reads; finite).
    if (tid == 2)
        *(float4*)(smem + bytes) = make_float4(0.f, 0.f, 0.f, 0.f);
    if (tid == 3)
        *(float4*)(smem + BUFSTRIDE + bytes) = make_float4(0.f, 0.f, 0.f, 0.f);
    __syncthreads();

    const char* srcq = (const char*)(image + (size_t)img * NCH * PLANE
                                           + (size_t)q * QROWS * IW);
    auto issue = [&](int t) {
        const int b = t & 1;
        const char* src = srcq + (size_t)(ch0 + t) * (PLANE * 4);
        const uint32_t mb = mbar + 8 * b;
        asm volatile("mbarrier.arrive.expect_tx.shared.b64 _, [%0], %1;"
                     :: "r"(mb), "r"(bytes) : "memory");
        asm volatile(
            "cp.async.bulk.shared::cta.global.mbarrier::complete_tx::bytes "
            "[%0], [%1], %2, [%3];"
            :: "r"(smem_b + b * BUFSTRIDE), "l"(src), "r"(bytes), "r"(mb)
            : "memory");
    };

    if (tid == 0) { issue(0); issue(1); }   // prime depth-2 pipeline

    const int ne = d_nent[img * NQ + q];
    const uint4* gent = d_ent + (img * NQ + q) * CAP;

    const int e0  = tid / CROP;        // 0..63
    const int col = tid - e0 * CROP;   // 0..13

    #pragma unroll
    for (int t = 0; t < TILES; ++t) {
        const int b = t & 1;
        const int parity = (t >> 1) & 1;
        const uint32_t mb = mbar + 8 * b;
        asm volatile(
            "{\n\t.reg .pred P;\n"
            "W%=:\n\t"
            "mbarrier.try_wait.parity.shared.b64 P, [%0], %1;\n\t"
            "@P bra D%=;\n\t"
            "bra W%=;\n"
            "D%=:\n\t}"
            :: "r"(mb), "r"(parity) : "memory");

        const char* planeb = smem + b * BUFSTRIDE;
        float* outb = out + (size_t)(ch0 + t) * POS + col;

        for (int e = e0; e < ne; e += EGRP) {
            const uint4 E = __ldg(gent + e);                 // L1-hot after t=0
            const uint2 tx = __ldg(d_xtab + (E.w & 0xFFFFu) + col);

            const char* r0 = planeb + (E.x & ~1u) + (tx.x & 255u) * 4;
            const char* r1 = r0 + (E.w >> 16);
            const float tl = *(const float*)r0;
            const float tr = *(const float*)(r0 + 4);
            const float bl = *(const float*)r1;
            const float br = *(const float*)(r1 + 4);

            const float lx = __uint_as_float(tx.y);
            const float ly = __uint_as_float(E.z);
            const float top = fmaf(tr - tl, lx, tl);
            const float bot = fmaf(br - bl, lx, bl);
            float val = fmaf(bot - top, ly, top);
            if (!(E.x & (tx.x >> 8) & 1u)) val = 0.0f;

            __stcs(outb + E.y, val);
        }

        if (t + 2 < TILES) {
            __syncthreads();          // buffer b fully consumed by all threads
            if (tid == 0) issue(t + 2);
        }
    }
}

extern "C" void kernel_launch(void* const* d_in, const int* in_sizes, int n_in,
                              void* d_out, int out_size)
{
    const float* image   = (const float*)d_in[0];
    const float* boxes   = (const float*)d_in[1];
    const int*   box_idx = (const int*)d_in[2];
    float*       out     = (float*)d_out;

    static void* nent_addr = nullptr;
    if (!nent_addr) {
        cudaGetSymbolAddress(&nent_addr, d_nent);
        cudaFuncSetAttribute(crop_resize_kernel,
                             cudaFuncAttributeMaxDynamicSharedMemorySize,
                             SM_BYTES);
    }

    cudaMemsetAsync(nent_addr, 0, NIMG * NQ * sizeof(int));
    prep_kernel<<<NBOX, 32>>>(boxes, box_idx);
    crop_resize_kernel<<<NIMG * (NCH / TILES) * NQ, TPB, SM_BYTES>>>(image, out);
}